// round 3
// baseline (speedup 1.0000x reference)
#include <cuda_runtime.h>

// InversePoseMatrixLayer: out = [R^T | -R^T t] for 4M poses (3x4 fp32 each).
//
// R2: warp-shuffle transpose, zero shared memory.
// 3 lanes per pose. Lane l loads float4 vec (30*warp + l) -- fully coalesced,
// 480 contiguous bytes per warp (lanes 30,31 idle; 32B-sector aligned so no
// wasted DRAM traffic). Lane holds row r = l%3 of pose l/3. Transpose via
// 12 SHFL.SYNC, then one coalesced STG.128 per lane. L1TEX now carries only
// the minimal global wavefronts; DRAM is the sole limiter.

#define THREADS      256
#define WARPS_PER_BLK (THREADS / 32)
#define VECS_PER_BLK (WARPS_PER_BLK * 30)   // 240 float4s per block

__global__ __launch_bounds__(THREADS) void inverse_pose_kernel(
    const float4* __restrict__ in, float4* __restrict__ out, int n_vec)
{
    const int lane   = threadIdx.x & 31;
    const int warp   = (blockIdx.x * WARPS_PER_BLK) + (threadIdx.x >> 5);
    const int vec    = warp * 30 + lane;
    const bool active = (lane < 30) && (vec < n_vec);

    float4 v = make_float4(0.f, 0.f, 0.f, 0.f);
    if (active) v = in[vec];

    const int r  = lane % 3;          // which row of the pose this lane holds
    const int s0 = lane - r;          // lane holding row 0 of my pose

    // Broadcast all four components from the three lanes of my pose group.
    const unsigned m = 0xFFFFFFFFu;
    float x0 = __shfl_sync(m, v.x, s0 + 0), x1 = __shfl_sync(m, v.x, s0 + 1), x2 = __shfl_sync(m, v.x, s0 + 2);
    float y0 = __shfl_sync(m, v.y, s0 + 0), y1 = __shfl_sync(m, v.y, s0 + 1), y2 = __shfl_sync(m, v.y, s0 + 2);
    float z0 = __shfl_sync(m, v.z, s0 + 0), z1 = __shfl_sync(m, v.z, s0 + 1), z2 = __shfl_sync(m, v.z, s0 + 2);
    float w0 = __shfl_sync(m, v.w, s0 + 0), w1 = __shfl_sync(m, v.w, s0 + 1), w2 = __shfl_sync(m, v.w, s0 + 2);

    // a_j = R[j][r] : component r of row j.
    const float a0 = (r == 0) ? x0 : (r == 1) ? y0 : z0;
    const float a1 = (r == 0) ? x1 : (r == 1) ? y1 : z1;
    const float a2 = (r == 0) ? x2 : (r == 1) ? y2 : z2;

    // t_inv[r] = -(R[0][r]*t0 + R[1][r]*t1 + R[2][r]*t2)
    const float ti = -(a0 * w0 + a1 * w1 + a2 * w2);

    if (active)
        out[vec] = make_float4(a0, a1, a2, ti);
}

extern "C" void kernel_launch(void* const* d_in, const int* in_sizes, int n_in,
                              void* d_out, int out_size)
{
    const float4* in = (const float4*)d_in[0];
    float4* out = (float4*)d_out;
    const int n_vec = in_sizes[0] / 4;   // total float4 count (n_poses * 3)

    const int blocks = (n_vec + VECS_PER_BLK - 1) / VECS_PER_BLK;
    inverse_pose_kernel<<<blocks, THREADS>>>(in, out, n_vec);
}

// round 4
// speedup vs baseline: 1.0993x; 1.0993x over previous
#include <cuda_runtime.h>
#include <cstdint>

// InversePoseMatrixLayer: out = [R^T | -R^T t] for 4M poses (3x4 fp32 each).
//
// R3: TMA 1D bulk copies (cp.async.bulk) for ALL global traffic -- zero
// per-thread global wavefronts. Threads only do the smem-local transform:
// 3x LDS.128 + 3x STS.128 per pose (stride-48B pattern is bank-conflict-free:
// per 8-lane phase the start banks {0,12,24,4,16,28,8,20} tile all 32 banks).
// L1/MIO cost drops from ~72 cyc to ~24 cyc per warp per 3072B of traffic,
// leaving DRAM/LTS as the sole limiter.

#define THREADS         256
#define POSES_PER_BLOCK 256
#define TILE_BYTES      (POSES_PER_BLOCK * 48)   // 12288

__device__ __forceinline__ uint32_t smem_u32(const void* p) {
    uint32_t a;
    asm("{ .reg .u64 t; cvta.to.shared.u64 t, %1; cvt.u32.u64 %0, t; }"
        : "=r"(a) : "l"(p));
    return a;
}

__global__ __launch_bounds__(THREADS) void inverse_pose_kernel(
    const char* __restrict__ in, char* __restrict__ out, int n_poses)
{
    __shared__ __align__(128) float4 tile[POSES_PER_BLOCK * 3];
    __shared__ __align__(8) uint64_t mbar;

    const int tid = threadIdx.x;
    const long long pose_base = (long long)blockIdx.x * POSES_PER_BLOCK;
    int poses_here = n_poses - (int)pose_base;
    if (poses_here > POSES_PER_BLOCK) poses_here = POSES_PER_BLOCK;
    const unsigned bytes = (unsigned)poses_here * 48u;   // multiple of 16

    const uint32_t s_tile = smem_u32(tile);
    const uint32_t s_mbar = smem_u32(&mbar);

    if (tid == 0) {
        asm volatile("mbarrier.init.shared.b64 [%0], %1;"
                     :: "r"(s_mbar), "r"(1u) : "memory");
    }
    __syncthreads();

    if (tid == 0) {
        asm volatile("mbarrier.arrive.expect_tx.shared.b64 _, [%0], %1;"
                     :: "r"(s_mbar), "r"(bytes) : "memory");
        asm volatile(
            "cp.async.bulk.shared::cta.global.mbarrier::complete_tx::bytes "
            "[%0], [%1], %2, [%3];"
            :: "r"(s_tile), "l"(in + pose_base * 48), "r"(bytes), "r"(s_mbar)
            : "memory");
    }

    // Wait for the bulk load (phase 0).
    {
        uint32_t done;
        asm volatile(
            "{\n\t"
            ".reg .pred p;\n\t"
            "mbarrier.try_wait.parity.shared.b64 p, [%1], %2;\n\t"
            "selp.b32 %0, 1, 0, p;\n\t"
            "}"
            : "=r"(done) : "r"(s_mbar), "r"(0u) : "memory");
        while (!done) {
            asm volatile(
                "{\n\t"
                ".reg .pred p;\n\t"
                "mbarrier.try_wait.parity.shared.b64 p, [%1], %2, 0x989680;\n\t"
                "selp.b32 %0, 1, 0, p;\n\t"
                "}"
                : "=r"(done) : "r"(s_mbar), "r"(0u) : "memory");
        }
    }

    // In-place pose inverse: thread t owns smem slots {3t, 3t+1, 3t+2}.
    if (tid < poses_here) {
        const float4 r0 = tile[3 * tid + 0];   // (R00, R01, R02, t0)
        const float4 r1 = tile[3 * tid + 1];   // (R10, R11, R12, t1)
        const float4 r2 = tile[3 * tid + 2];   // (R20, R21, R22, t2)

        const float ti0 = -(r0.x * r0.w + r1.x * r1.w + r2.x * r2.w);
        const float ti1 = -(r0.y * r0.w + r1.y * r1.w + r2.y * r2.w);
        const float ti2 = -(r0.z * r0.w + r1.z * r1.w + r2.z * r2.w);

        tile[3 * tid + 0] = make_float4(r0.x, r1.x, r2.x, ti0);
        tile[3 * tid + 1] = make_float4(r0.y, r1.y, r2.y, ti1);
        tile[3 * tid + 2] = make_float4(r0.z, r1.z, r2.z, ti2);
    }

    // Make generic-proxy smem writes visible to the async proxy, then sync.
    asm volatile("fence.proxy.async.shared::cta;" ::: "memory");
    __syncthreads();

    if (tid == 0) {
        asm volatile(
            "cp.async.bulk.global.shared::cta.bulk_group [%0], [%1], %2;"
            :: "l"(out + pose_base * 48), "r"(s_tile), "r"(bytes)
            : "memory");
        asm volatile("cp.async.bulk.commit_group;" ::: "memory");
        // Keep the CTA (and its smem) alive until TMA has read the tile.
        asm volatile("cp.async.bulk.wait_group.read 0;" ::: "memory");
    }
}

extern "C" void kernel_launch(void* const* d_in, const int* in_sizes, int n_in,
                              void* d_out, int out_size)
{
    const char* in = (const char*)d_in[0];
    char* out = (char*)d_out;
    const int n_poses = in_sizes[0] / 12;   // 12 floats per pose

    const int blocks = (n_poses + POSES_PER_BLOCK - 1) / POSES_PER_BLOCK;
    inverse_pose_kernel<<<blocks, THREADS>>>(in, out, n_poses);
}